// round 3
// baseline (speedup 1.0000x reference)
#include <cuda_runtime.h>

#define Tn 512
#define Sn 1024
#define Bn 16
#define An 512
#define Hn 8
#define ROWPITCH (Bn * An) /* 8192 floats between consecutive t or s rows */

// Scratch (allocation-free per harness rules)
__device__ float g_vh[(size_t)Sn * Bn * An];    // v-projected keys, same layout as keys
__device__ float g_vals[(size_t)Tn * Bn * An];  // attention output pre o-proj

// Load a ROWSx64 fp32 tile (global row pitch = gpitch floats) TRANSPOSED into
// smem sm[j][r] with row pitch PITCH floats (PITCH*4 % 16 == 0). 256 threads.
template <int ROWS, int PITCH>
__device__ __forceinline__ void load_T(float* sm, const float* __restrict__ g,
                                       int gpitch, float scale) {
#pragma unroll
    for (int i = threadIdx.x; i < ROWS * 16; i += 256) {
        int r = i >> 4;
        int j = (i & 15) << 2;
        float4 v = *(const float4*)(g + (size_t)r * gpitch + j);
        sm[(j + 0) * PITCH + r] = v.x * scale;
        sm[(j + 1) * PITCH + r] = v.y * scale;
        sm[(j + 2) * PITCH + r] = v.z * scale;
        sm[(j + 3) * PITCH + r] = v.w * scale;
    }
}

// ---------------------------------------------------------------------------
// Kernel 1: Vh[r][i] = sum_j K2d[r][j] * vw[i][j] + vb[i]
// K2d = keys viewed as [S*B*H, 64]. Tile: 256 rows x 64 cols, 8x8 per thread.
// ---------------------------------------------------------------------------
__global__ void __launch_bounds__(256) vproj_kernel(const float* __restrict__ keys,
                                                    const float* __restrict__ vw,
                                                    const float* __restrict__ vb) {
    extern __shared__ float smv[];
    float* a_sm = smv;             // [64][264] keys chunk transposed
    float* w_sm = smv + 64 * 264;  // [64][68]  vw transposed

    const size_t rowbase = (size_t)blockIdx.x * 256;
    const int tx = threadIdx.x & 7, ty = threadIdx.x >> 3;
    const int r0 = ty * 8, c0 = tx * 8;

    load_T<256, 264>(a_sm, keys + rowbase * 64, 64, 1.0f);
    load_T<64, 68>(w_sm, vw, 64, 1.0f);
    __syncthreads();

    float acc[8][8];
    float4 b0 = *(const float4*)(vb + c0);
    float4 b1 = *(const float4*)(vb + c0 + 4);
#pragma unroll
    for (int rr = 0; rr < 8; rr++) {
        acc[rr][0] = b0.x; acc[rr][1] = b0.y; acc[rr][2] = b0.z; acc[rr][3] = b0.w;
        acc[rr][4] = b1.x; acc[rr][5] = b1.y; acc[rr][6] = b1.z; acc[rr][7] = b1.w;
    }

#pragma unroll 4
    for (int j = 0; j < 64; j++) {
        float a[8], w[8];
        *(float4*)&a[0] = *(const float4*)&a_sm[j * 264 + r0];
        *(float4*)&a[4] = *(const float4*)&a_sm[j * 264 + r0 + 4];
        *(float4*)&w[0] = *(const float4*)&w_sm[j * 68 + c0];
        *(float4*)&w[4] = *(const float4*)&w_sm[j * 68 + c0 + 4];
#pragma unroll
        for (int rr = 0; rr < 8; rr++)
#pragma unroll
            for (int cc = 0; cc < 8; cc++) acc[rr][cc] = fmaf(a[rr], w[cc], acc[rr][cc]);
    }

#pragma unroll
    for (int rr = 0; rr < 8; rr++) {
        float* o = g_vh + (rowbase + r0 + rr) * 64 + c0;
        *(float4*)o = make_float4(acc[rr][0], acc[rr][1], acc[rr][2], acc[rr][3]);
        *(float4*)(o + 4) = make_float4(acc[rr][4], acc[rr][5], acc[rr][6], acc[rr][7]);
    }
}

// ---------------------------------------------------------------------------
// Kernel 2: flash attention per (b, h, t-tile of 128). 256 threads.
// Score tile 128x128 (8x8/thread); PV output 128x64 (8x4/thread).
// Mask read as 32-bit words (nonzero = keep).
// ---------------------------------------------------------------------------
__global__ void __launch_bounds__(256) attn_kernel(const float* __restrict__ q,
                                                   const float* __restrict__ k,
                                                   const unsigned int* __restrict__ mask) {
    extern __shared__ float sm[];
    float* q_sm = sm;                  // [64][132] Q^T, pre-scaled by 1/8
    float* k_sm = sm + 64 * 132;       // [64][132] K^T
    float* v_sm = sm + 2 * 64 * 132;   // [128][68] V row-major
    float* p_sm = v_sm + 128 * 68;     // [128][132] P transposed [s][r]

    const int tid = threadIdx.x;
    const int t0 = blockIdx.x * 128;
    const int h = blockIdx.y;
    const int b = blockIdx.z;
    const int tx = tid & 15, ty = tid >> 4;
    const int r0 = ty * 8;        // 16 ty values -> 128 rows
    const int cq0 = tx * 8;       // 16 tx values -> 128 score cols
    const int cv0 = tx * 4;       // 16 tx values -> 64 value cols

    load_T<128, 132>(q_sm, q + ((size_t)t0 * Bn + b) * An + h * 64, ROWPITCH, 0.125f);

    float oacc[8][4];
#pragma unroll
    for (int rr = 0; rr < 8; rr++)
#pragma unroll
        for (int cc = 0; cc < 4; cc++) oacc[rr][cc] = 0.0f;
    float mrun[8], lrun[8];
#pragma unroll
    for (int rr = 0; rr < 8; rr++) { mrun[rr] = -1e30f; lrun[rr] = 0.0f; }

    const unsigned int* mbase = mask + ((size_t)b * Tn + t0 + r0) * Sn + cq0;

    for (int st = 0; st < Sn / 128; st++) {
        const int s0 = st * 128;
        __syncthreads();  // prior readers of k_sm/v_sm/p_sm done (covers q_sm load too)

        load_T<128, 132>(k_sm, k + ((size_t)s0 * Bn + b) * An + h * 64, ROWPITCH, 1.0f);
        {
            const float* vsrc = g_vh + ((size_t)s0 * Bn + b) * An + h * 64;
#pragma unroll
            for (int i = tid; i < 128 * 16; i += 256) {
                int r = i >> 4;
                int j = (i & 15) << 2;
                *(float4*)&v_sm[r * 68 + j] = *(const float4*)(vsrc + (size_t)r * ROWPITCH + j);
            }
        }
        __syncthreads();

        // ---- scores ----
        float sacc[8][8];
#pragma unroll
        for (int rr = 0; rr < 8; rr++)
#pragma unroll
            for (int cc = 0; cc < 8; cc++) sacc[rr][cc] = 0.0f;
#pragma unroll 4
        for (int j = 0; j < 64; j++) {
            float a[8], bb[8];
            *(float4*)&a[0] = *(const float4*)&q_sm[j * 132 + r0];
            *(float4*)&a[4] = *(const float4*)&q_sm[j * 132 + r0 + 4];
            *(float4*)&bb[0] = *(const float4*)&k_sm[j * 132 + cq0];
            *(float4*)&bb[4] = *(const float4*)&k_sm[j * 132 + cq0 + 4];
#pragma unroll
            for (int rr = 0; rr < 8; rr++)
#pragma unroll
                for (int cc = 0; cc < 8; cc++) sacc[rr][cc] = fmaf(a[rr], bb[cc], sacc[rr][cc]);
        }

        // ---- mask ----
#pragma unroll
        for (int rr = 0; rr < 8; rr++) {
            const unsigned int* mrow = mbase + (size_t)rr * Sn + s0;
            uint4 m0 = *(const uint4*)mrow;
            uint4 m1 = *(const uint4*)(mrow + 4);
            if (!m0.x) sacc[rr][0] = -1e30f;
            if (!m0.y) sacc[rr][1] = -1e30f;
            if (!m0.z) sacc[rr][2] = -1e30f;
            if (!m0.w) sacc[rr][3] = -1e30f;
            if (!m1.x) sacc[rr][4] = -1e30f;
            if (!m1.y) sacc[rr][5] = -1e30f;
            if (!m1.z) sacc[rr][6] = -1e30f;
            if (!m1.w) sacc[rr][7] = -1e30f;
        }

        // ---- online softmax (rows shared by 16 lanes: tx group) ----
#pragma unroll
        for (int rr = 0; rr < 8; rr++) {
            float ml = sacc[rr][0];
#pragma unroll
            for (int cc = 1; cc < 8; cc++) ml = fmaxf(ml, sacc[rr][cc]);
#pragma unroll
            for (int off = 8; off; off >>= 1) ml = fmaxf(ml, __shfl_xor_sync(0xffffffffu, ml, off));
            float mnew = fmaxf(mrun[rr], ml);
            float alpha = __expf(mrun[rr] - mnew);
            mrun[rr] = mnew;
            float ls = 0.0f;
#pragma unroll
            for (int cc = 0; cc < 8; cc++) {
                float p = __expf(sacc[rr][cc] - mnew);
                sacc[rr][cc] = p;
                ls += p;
            }
#pragma unroll
            for (int off = 8; off; off >>= 1) ls += __shfl_xor_sync(0xffffffffu, ls, off);
            lrun[rr] = lrun[rr] * alpha + ls;
#pragma unroll
            for (int cc = 0; cc < 4; cc++) oacc[rr][cc] *= alpha;
        }

        __syncthreads();  // all reads of k_sm (scores) done
        // write P transposed: p_sm[s][r]
#pragma unroll
        for (int cc = 0; cc < 8; cc++) {
            *(float4*)&p_sm[(cq0 + cc) * 132 + r0] =
                make_float4(sacc[0][cc], sacc[1][cc], sacc[2][cc], sacc[3][cc]);
            *(float4*)&p_sm[(cq0 + cc) * 132 + r0 + 4] =
                make_float4(sacc[4][cc], sacc[5][cc], sacc[6][cc], sacc[7][cc]);
        }
        __syncthreads();

        // ---- O += P @ V ----
#pragma unroll 4
        for (int s = 0; s < 128; s++) {
            float p8[8];
            *(float4*)&p8[0] = *(const float4*)&p_sm[s * 132 + r0];
            *(float4*)&p8[4] = *(const float4*)&p_sm[s * 132 + r0 + 4];
            float4 v4 = *(const float4*)&v_sm[s * 68 + cv0];
            float vv[4] = {v4.x, v4.y, v4.z, v4.w};
#pragma unroll
            for (int rr = 0; rr < 8; rr++)
#pragma unroll
                for (int cc = 0; cc < 4; cc++) oacc[rr][cc] = fmaf(p8[rr], vv[cc], oacc[rr][cc]);
        }
    }

    // epilogue: normalize and store
#pragma unroll
    for (int rr = 0; rr < 8; rr++) {
        float inv = 1.0f / lrun[rr];
        float* o = g_vals + ((size_t)(t0 + r0 + rr) * Bn + b) * An + h * 64 + cv0;
        *(float4*)o = make_float4(oacc[rr][0] * inv, oacc[rr][1] * inv,
                                  oacc[rr][2] * inv, oacc[rr][3] * inv);
    }
}

// ---------------------------------------------------------------------------
// Kernel 3: out[r][i] = sum_j vals[r][j] * ow[i][j] + ob[i]. Tiles 128x128,
// 8x8 per thread, k in chunks of 64.
// ---------------------------------------------------------------------------
__global__ void __launch_bounds__(256) oproj_kernel(const float* __restrict__ ow,
                                                    const float* __restrict__ ob,
                                                    float* __restrict__ out) {
    extern __shared__ float smo[];
    float* a_sm = smo;             // [64][132] vals chunk transposed
    float* b_sm = smo + 64 * 132;  // [64][132] ow chunk transposed

    const int tx = threadIdx.x & 15, ty = threadIdx.x >> 4;
    const int r0 = ty * 8, c0 = tx * 8;
    const size_t rowbase = (size_t)blockIdx.x * 128;
    const int i0 = blockIdx.y * 128;

    float acc[8][8];
    float4 b0 = *(const float4*)(ob + i0 + c0);
    float4 b1 = *(const float4*)(ob + i0 + c0 + 4);
#pragma unroll
    for (int rr = 0; rr < 8; rr++) {
        acc[rr][0] = b0.x; acc[rr][1] = b0.y; acc[rr][2] = b0.z; acc[rr][3] = b0.w;
        acc[rr][4] = b1.x; acc[rr][5] = b1.y; acc[rr][6] = b1.z; acc[rr][7] = b1.w;
    }

    for (int kc = 0; kc < 8; kc++) {
        const int j0 = kc * 64;
        __syncthreads();
        load_T<128, 132>(a_sm, g_vals + rowbase * An + j0, An, 1.0f);
        load_T<128, 132>(b_sm, ow + (size_t)i0 * An + j0, An, 1.0f);
        __syncthreads();
#pragma unroll 4
        for (int j = 0; j < 64; j++) {
            float a[8], w[8];
            *(float4*)&a[0] = *(const float4*)&a_sm[j * 132 + r0];
            *(float4*)&a[4] = *(const float4*)&a_sm[j * 132 + r0 + 4];
            *(float4*)&w[0] = *(const float4*)&b_sm[j * 132 + c0];
            *(float4*)&w[4] = *(const float4*)&b_sm[j * 132 + c0 + 4];
#pragma unroll
            for (int rr = 0; rr < 8; rr++)
#pragma unroll
                for (int cc = 0; cc < 8; cc++) acc[rr][cc] = fmaf(a[rr], w[cc], acc[rr][cc]);
        }
    }

#pragma unroll
    for (int rr = 0; rr < 8; rr++) {
        float* o = out + (rowbase + r0 + rr) * An + i0 + c0;
        *(float4*)o = make_float4(acc[rr][0], acc[rr][1], acc[rr][2], acc[rr][3]);
        *(float4*)(o + 4) = make_float4(acc[rr][4], acc[rr][5], acc[rr][6], acc[rr][7]);
    }
}

// ---------------------------------------------------------------------------
extern "C" void kernel_launch(void* const* d_in, const int* in_sizes, int n_in,
                              void* d_out, int out_size) {
    const float* q = (const float*)d_in[0];
    const float* k = (const float*)d_in[1];
    const unsigned int* mask = (const unsigned int*)d_in[2];
    const float* vw = (const float*)d_in[3];
    const float* vb = (const float*)d_in[4];
    const float* ow = (const float*)d_in[5];
    const float* ob = (const float*)d_in[6];
    float* out = (float*)d_out;

    // 1) v-projection of keys: tiles of 256 rows
    const int vproj_smem = (64 * 264 + 64 * 68) * sizeof(float);  // 84992
    cudaFuncSetAttribute(vproj_kernel, cudaFuncAttributeMaxDynamicSharedMemorySize, vproj_smem);
    vproj_kernel<<<(Sn * Bn * Hn) / 256, 256, vproj_smem>>>(k, vw, vb);

    // 2) flash attention
    const int attn_smem = (2 * 64 * 132 + 128 * 68 + 128 * 132) * sizeof(float);  // 169984
    cudaFuncSetAttribute(attn_kernel, cudaFuncAttributeMaxDynamicSharedMemorySize, attn_smem);
    dim3 g2(Tn / 128, Hn, Bn);
    attn_kernel<<<g2, 256, attn_smem>>>(q, k, mask);

    // 3) output projection
    const int oproj_smem = 2 * 64 * 132 * sizeof(float);  // 67584
    cudaFuncSetAttribute(oproj_kernel, cudaFuncAttributeMaxDynamicSharedMemorySize, oproj_smem);
    dim3 g3((Tn * Bn) / 128, An / 128);
    oproj_kernel<<<g3, 256, oproj_smem>>>(ow, ob, out);
}

// round 4
// speedup vs baseline: 1.0016x; 1.0016x over previous
#include <cuda_runtime.h>

#define Tn 512
#define Sn 1024
#define Bn 16
#define An 512
#define Hn 8
#define ROWPITCH (Bn * An) /* 8192 floats between consecutive t or s rows */

// Scratch (allocation-free per harness rules)
__device__ float g_vh[(size_t)Sn * Bn * An];    // v-projected keys, same layout as keys
__device__ float g_vals[(size_t)Tn * Bn * An];  // attention output pre o-proj

// Load a ROWSx64 fp32 tile (global row pitch = gpitch floats) TRANSPOSED into
// smem sm[j][r] with row pitch PITCH floats (PITCH*4 % 16 == 0). 256 threads.
template <int ROWS, int PITCH>
__device__ __forceinline__ void load_T(float* sm, const float* __restrict__ g,
                                       int gpitch, float scale) {
#pragma unroll
    for (int i = threadIdx.x; i < ROWS * 16; i += 256) {
        int r = i >> 4;
        int j = (i & 15) << 2;
        float4 v = *(const float4*)(g + (size_t)r * gpitch + j);
        sm[(j + 0) * PITCH + r] = v.x * scale;
        sm[(j + 1) * PITCH + r] = v.y * scale;
        sm[(j + 2) * PITCH + r] = v.z * scale;
        sm[(j + 3) * PITCH + r] = v.w * scale;
    }
}

// ---------------------------------------------------------------------------
// Kernel 1: Vh[r][i] = sum_j K2d[r][j] * vw[i][j] + vb[i]
// K2d = keys viewed as [S*B*H, 64]. Tile: 256 rows x 64 cols, 8x8 per thread.
// ---------------------------------------------------------------------------
__global__ void __launch_bounds__(256) vproj_kernel(const float* __restrict__ keys,
                                                    const float* __restrict__ vw,
                                                    const float* __restrict__ vb) {
    extern __shared__ float smv[];
    float* a_sm = smv;             // [64][264] keys chunk transposed
    float* w_sm = smv + 64 * 264;  // [64][68]  vw transposed

    const size_t rowbase = (size_t)blockIdx.x * 256;
    const int tx = threadIdx.x & 7, ty = threadIdx.x >> 3;
    const int r0 = ty * 8, c0 = tx * 8;

    load_T<256, 264>(a_sm, keys + rowbase * 64, 64, 1.0f);
    load_T<64, 68>(w_sm, vw, 64, 1.0f);
    __syncthreads();

    float acc[8][8];
    float4 b0 = *(const float4*)(vb + c0);
    float4 b1 = *(const float4*)(vb + c0 + 4);
#pragma unroll
    for (int rr = 0; rr < 8; rr++) {
        acc[rr][0] = b0.x; acc[rr][1] = b0.y; acc[rr][2] = b0.z; acc[rr][3] = b0.w;
        acc[rr][4] = b1.x; acc[rr][5] = b1.y; acc[rr][6] = b1.z; acc[rr][7] = b1.w;
    }

#pragma unroll 4
    for (int j = 0; j < 64; j++) {
        float a[8], w[8];
        *(float4*)&a[0] = *(const float4*)&a_sm[j * 264 + r0];
        *(float4*)&a[4] = *(const float4*)&a_sm[j * 264 + r0 + 4];
        *(float4*)&w[0] = *(const float4*)&w_sm[j * 68 + c0];
        *(float4*)&w[4] = *(const float4*)&w_sm[j * 68 + c0 + 4];
#pragma unroll
        for (int rr = 0; rr < 8; rr++)
#pragma unroll
            for (int cc = 0; cc < 8; cc++) acc[rr][cc] = fmaf(a[rr], w[cc], acc[rr][cc]);
    }

#pragma unroll
    for (int rr = 0; rr < 8; rr++) {
        float* o = g_vh + (rowbase + r0 + rr) * 64 + c0;
        *(float4*)o = make_float4(acc[rr][0], acc[rr][1], acc[rr][2], acc[rr][3]);
        *(float4*)(o + 4) = make_float4(acc[rr][4], acc[rr][5], acc[rr][6], acc[rr][7]);
    }
}

// ---------------------------------------------------------------------------
// Kernel 2: flash attention per (b, h, t-tile of 128). 256 threads.
// Score tile 128x128 (8x8/thread); PV output 128x64 (8x4/thread).
// Mask read as 32-bit words (nonzero = keep).
// ---------------------------------------------------------------------------
__global__ void __launch_bounds__(256) attn_kernel(const float* __restrict__ q,
                                                   const float* __restrict__ k,
                                                   const unsigned int* __restrict__ mask) {
    extern __shared__ float sm[];
    float* q_sm = sm;                  // [64][132] Q^T, pre-scaled by 1/8
    float* k_sm = sm + 64 * 132;       // [64][132] K^T
    float* v_sm = sm + 2 * 64 * 132;   // [128][68] V row-major
    float* p_sm = v_sm + 128 * 68;     // [128][132] P transposed [s][r]

    const int tid = threadIdx.x;
    const int t0 = blockIdx.x * 128;
    const int h = blockIdx.y;
    const int b = blockIdx.z;
    const int tx = tid & 15, ty = tid >> 4;
    const int r0 = ty * 8;        // 16 ty values -> 128 rows
    const int cq0 = tx * 8;       // 16 tx values -> 128 score cols
    const int cv0 = tx * 4;       // 16 tx values -> 64 value cols

    load_T<128, 132>(q_sm, q + ((size_t)t0 * Bn + b) * An + h * 64, ROWPITCH, 0.125f);

    float oacc[8][4];
#pragma unroll
    for (int rr = 0; rr < 8; rr++)
#pragma unroll
        for (int cc = 0; cc < 4; cc++) oacc[rr][cc] = 0.0f;
    float mrun[8], lrun[8];
#pragma unroll
    for (int rr = 0; rr < 8; rr++) { mrun[rr] = -1e30f; lrun[rr] = 0.0f; }

    const unsigned int* mbase = mask + ((size_t)b * Tn + t0 + r0) * Sn + cq0;

    for (int st = 0; st < Sn / 128; st++) {
        const int s0 = st * 128;
        __syncthreads();  // prior readers of k_sm/v_sm/p_sm done (covers q_sm load too)

        load_T<128, 132>(k_sm, k + ((size_t)s0 * Bn + b) * An + h * 64, ROWPITCH, 1.0f);
        {
            const float* vsrc = g_vh + ((size_t)s0 * Bn + b) * An + h * 64;
#pragma unroll
            for (int i = tid; i < 128 * 16; i += 256) {
                int r = i >> 4;
                int j = (i & 15) << 2;
                *(float4*)&v_sm[r * 68 + j] = *(const float4*)(vsrc + (size_t)r * ROWPITCH + j);
            }
        }
        __syncthreads();

        // ---- scores ----
        float sacc[8][8];
#pragma unroll
        for (int rr = 0; rr < 8; rr++)
#pragma unroll
            for (int cc = 0; cc < 8; cc++) sacc[rr][cc] = 0.0f;
#pragma unroll 4
        for (int j = 0; j < 64; j++) {
            float a[8], bb[8];
            *(float4*)&a[0] = *(const float4*)&q_sm[j * 132 + r0];
            *(float4*)&a[4] = *(const float4*)&q_sm[j * 132 + r0 + 4];
            *(float4*)&bb[0] = *(const float4*)&k_sm[j * 132 + cq0];
            *(float4*)&bb[4] = *(const float4*)&k_sm[j * 132 + cq0 + 4];
#pragma unroll
            for (int rr = 0; rr < 8; rr++)
#pragma unroll
                for (int cc = 0; cc < 8; cc++) sacc[rr][cc] = fmaf(a[rr], bb[cc], sacc[rr][cc]);
        }

        // ---- mask ----
#pragma unroll
        for (int rr = 0; rr < 8; rr++) {
            const unsigned int* mrow = mbase + (size_t)rr * Sn + s0;
            uint4 m0 = *(const uint4*)mrow;
            uint4 m1 = *(const uint4*)(mrow + 4);
            if (!m0.x) sacc[rr][0] = -1e30f;
            if (!m0.y) sacc[rr][1] = -1e30f;
            if (!m0.z) sacc[rr][2] = -1e30f;
            if (!m0.w) sacc[rr][3] = -1e30f;
            if (!m1.x) sacc[rr][4] = -1e30f;
            if (!m1.y) sacc[rr][5] = -1e30f;
            if (!m1.z) sacc[rr][6] = -1e30f;
            if (!m1.w) sacc[rr][7] = -1e30f;
        }

        // ---- online softmax (rows shared by 16 lanes: tx group) ----
#pragma unroll
        for (int rr = 0; rr < 8; rr++) {
            float ml = sacc[rr][0];
#pragma unroll
            for (int cc = 1; cc < 8; cc++) ml = fmaxf(ml, sacc[rr][cc]);
#pragma unroll
            for (int off = 8; off; off >>= 1) ml = fmaxf(ml, __shfl_xor_sync(0xffffffffu, ml, off));
            float mnew = fmaxf(mrun[rr], ml);
            float alpha = __expf(mrun[rr] - mnew);
            mrun[rr] = mnew;
            float ls = 0.0f;
#pragma unroll
            for (int cc = 0; cc < 8; cc++) {
                float p = __expf(sacc[rr][cc] - mnew);
                sacc[rr][cc] = p;
                ls += p;
            }
#pragma unroll
            for (int off = 8; off; off >>= 1) ls += __shfl_xor_sync(0xffffffffu, ls, off);
            lrun[rr] = lrun[rr] * alpha + ls;
#pragma unroll
            for (int cc = 0; cc < 4; cc++) oacc[rr][cc] *= alpha;
        }

        __syncthreads();  // all reads of k_sm (scores) done
        // write P transposed: p_sm[s][r]
#pragma unroll
        for (int cc = 0; cc < 8; cc++) {
            *(float4*)&p_sm[(cq0 + cc) * 132 + r0] =
                make_float4(sacc[0][cc], sacc[1][cc], sacc[2][cc], sacc[3][cc]);
            *(float4*)&p_sm[(cq0 + cc) * 132 + r0 + 4] =
                make_float4(sacc[4][cc], sacc[5][cc], sacc[6][cc], sacc[7][cc]);
        }
        __syncthreads();

        // ---- O += P @ V ----
#pragma unroll 4
        for (int s = 0; s < 128; s++) {
            float p8[8];
            *(float4*)&p8[0] = *(const float4*)&p_sm[s * 132 + r0];
            *(float4*)&p8[4] = *(const float4*)&p_sm[s * 132 + r0 + 4];
            float4 v4 = *(const float4*)&v_sm[s * 68 + cv0];
            float vv[4] = {v4.x, v4.y, v4.z, v4.w};
#pragma unroll
            for (int rr = 0; rr < 8; rr++)
#pragma unroll
                for (int cc = 0; cc < 4; cc++) oacc[rr][cc] = fmaf(p8[rr], vv[cc], oacc[rr][cc]);
        }
    }

    // epilogue: normalize and store
#pragma unroll
    for (int rr = 0; rr < 8; rr++) {
        float inv = 1.0f / lrun[rr];
        float* o = g_vals + ((size_t)(t0 + r0 + rr) * Bn + b) * An + h * 64 + cv0;
        *(float4*)o = make_float4(oacc[rr][0] * inv, oacc[rr][1] * inv,
                                  oacc[rr][2] * inv, oacc[rr][3] * inv);
    }
}

// ---------------------------------------------------------------------------
// Kernel 3: out[r][i] = sum_j vals[r][j] * ow[i][j] + ob[i]. Tiles 128x128,
// 8x8 per thread, k in chunks of 64.
// ---------------------------------------------------------------------------
__global__ void __launch_bounds__(256) oproj_kernel(const float* __restrict__ ow,
                                                    const float* __restrict__ ob,
                                                    float* __restrict__ out) {
    extern __shared__ float smo[];
    float* a_sm = smo;             // [64][132] vals chunk transposed
    float* b_sm = smo + 64 * 132;  // [64][132] ow chunk transposed

    const int tx = threadIdx.x & 15, ty = threadIdx.x >> 4;
    const int r0 = ty * 8, c0 = tx * 8;
    const size_t rowbase = (size_t)blockIdx.x * 128;
    const int i0 = blockIdx.y * 128;

    float acc[8][8];
    float4 b0 = *(const float4*)(ob + i0 + c0);
    float4 b1 = *(const float4*)(ob + i0 + c0 + 4);
#pragma unroll
    for (int rr = 0; rr < 8; rr++) {
        acc[rr][0] = b0.x; acc[rr][1] = b0.y; acc[rr][2] = b0.z; acc[rr][3] = b0.w;
        acc[rr][4] = b1.x; acc[rr][5] = b1.y; acc[rr][6] = b1.z; acc[rr][7] = b1.w;
    }

    for (int kc = 0; kc < 8; kc++) {
        const int j0 = kc * 64;
        __syncthreads();
        load_T<128, 132>(a_sm, g_vals + rowbase * An + j0, An, 1.0f);
        load_T<128, 132>(b_sm, ow + (size_t)i0 * An + j0, An, 1.0f);
        __syncthreads();
#pragma unroll 4
        for (int j = 0; j < 64; j++) {
            float a[8], w[8];
            *(float4*)&a[0] = *(const float4*)&a_sm[j * 132 + r0];
            *(float4*)&a[4] = *(const float4*)&a_sm[j * 132 + r0 + 4];
            *(float4*)&w[0] = *(const float4*)&b_sm[j * 132 + c0];
            *(float4*)&w[4] = *(const float4*)&b_sm[j * 132 + c0 + 4];
#pragma unroll
            for (int rr = 0; rr < 8; rr++)
#pragma unroll
                for (int cc = 0; cc < 8; cc++) acc[rr][cc] = fmaf(a[rr], w[cc], acc[rr][cc]);
        }
    }

#pragma unroll
    for (int rr = 0; rr < 8; rr++) {
        float* o = out + (rowbase + r0 + rr) * An + i0 + c0;
        *(float4*)o = make_float4(acc[rr][0], acc[rr][1], acc[rr][2], acc[rr][3]);
        *(float4*)(o + 4) = make_float4(acc[rr][4], acc[rr][5], acc[rr][6], acc[rr][7]);
    }
}

// ---------------------------------------------------------------------------
extern "C" void kernel_launch(void* const* d_in, const int* in_sizes, int n_in,
                              void* d_out, int out_size) {
    const float* q = (const float*)d_in[0];
    const float* k = (const float*)d_in[1];
    const unsigned int* mask = (const unsigned int*)d_in[2];
    const float* vw = (const float*)d_in[3];
    const float* vb = (const float*)d_in[4];
    const float* ow = (const float*)d_in[5];
    const float* ob = (const float*)d_in[6];
    float* out = (float*)d_out;

    // 1) v-projection of keys: tiles of 256 rows
    const int vproj_smem = (64 * 264 + 64 * 68) * sizeof(float);  // 84992
    cudaFuncSetAttribute(vproj_kernel, cudaFuncAttributeMaxDynamicSharedMemorySize, vproj_smem);
    vproj_kernel<<<(Sn * Bn * Hn) / 256, 256, vproj_smem>>>(k, vw, vb);

    // 2) flash attention
    const int attn_smem = (2 * 64 * 132 + 128 * 68 + 128 * 132) * sizeof(float);  // 169984
    cudaFuncSetAttribute(attn_kernel, cudaFuncAttributeMaxDynamicSharedMemorySize, attn_smem);
    dim3 g2(Tn / 128, Hn, Bn);
    attn_kernel<<<g2, 256, attn_smem>>>(q, k, mask);

    // 3) output projection
    const int oproj_smem = 2 * 64 * 132 * sizeof(float);  // 67584
    cudaFuncSetAttribute(oproj_kernel, cudaFuncAttributeMaxDynamicSharedMemorySize, oproj_smem);
    dim3 g3((Tn * Bn) / 128, An / 128);
    oproj_kernel<<<g3, 256, oproj_smem>>>(ow, ob, out);
}

// round 5
// speedup vs baseline: 1.4707x; 1.4684x over previous
#include <cuda_runtime.h>

#define Tn 512
#define Sn 1024
#define Bn 16
#define An 512
#define Hn 8

// ---------------- scratch (allocation-free) -----------------
// All bf16 data: uint2 = {x: hi-plane bf16x2, y: lo-plane bf16x2}; each bf16x2
// packs (k even -> lo16, k odd -> hi16).
__device__ uint2 g_q[128 * 512 * 32];   // [bh][t][kpair]   Q/8
__device__ uint2 g_k[128 * 1024 * 32];  // [bh][s][kpair]
__device__ uint2 g_vt[128 * 64 * 512];  // [bh][d][spair]   Vh transposed
__device__ uint2 g_va[8192 * 256];      // [t*16+b][Apair]  attn out
__device__ uint2 g_ow[512 * 256];       // [n][kpair]
__device__ float g_vh[(size_t)Sn * Bn * An];  // fp32 Vh, layout as keys

// ---------------- helpers -----------------
__device__ __forceinline__ unsigned pk(float lo, float hi) {
    unsigned r;
    asm("cvt.rn.bf16x2.f32 %0, %1, %2;" : "=r"(r) : "f"(hi), "f"(lo));
    return r;
}
__device__ __forceinline__ float bflo(unsigned w) { return __uint_as_float(w << 16); }
__device__ __forceinline__ float bfhi(unsigned w) { return __uint_as_float(w & 0xFFFF0000u); }

// split (x0=k-even, x1=k-odd) -> hi-plane word (truncate) + lo-plane word (residual, rn)
__device__ __forceinline__ uint2 split2(float x0, float x1) {
    unsigned b0 = __float_as_uint(x0), b1 = __float_as_uint(x1);
    unsigned hi = __byte_perm(b0, b1, 0x7632);
    float r0 = x0 - __uint_as_float(b0 & 0xFFFF0000u);
    float r1 = x1 - __uint_as_float(b1 & 0xFFFF0000u);
    return make_uint2(hi, pk(r0, r1));
}

__device__ __forceinline__ void mma(float c[4], const unsigned a[4], unsigned b0, unsigned b1) {
    asm volatile(
        "mma.sync.aligned.m16n8k16.row.col.f32.bf16.bf16.f32 "
        "{%0,%1,%2,%3}, {%4,%5,%6,%7}, {%8,%9}, {%0,%1,%2,%3};\n"
        : "+f"(c[0]), "+f"(c[1]), "+f"(c[2]), "+f"(c[3])
        : "r"(a[0]), "r"(a[1]), "r"(a[2]), "r"(a[3]), "r"(b0), "r"(b1));
}

// ---------------- prep kernels -----------------
__global__ void __launch_bounds__(256) qprep_kernel(const float* __restrict__ q) {
    int idx = blockIdx.x * 256 + threadIdx.x;            // over 128*512*32
    int bh = idx >> 14, rem = idx & 16383;
    int t = rem >> 5, kp = rem & 31;
    int b = bh >> 3, h = bh & 7;
    float2 v = *(const float2*)(q + ((size_t)t * 16 + b) * 512 + h * 64 + 2 * kp);
    g_q[idx] = split2(v.x * 0.125f, v.y * 0.125f);
}

__global__ void __launch_bounds__(256) kprep_kernel(const float* __restrict__ k) {
    int idx = blockIdx.x * 256 + threadIdx.x;            // over 128*1024*32
    int bh = idx >> 15, rem = idx & 32767;
    int s = rem >> 5, kp = rem & 31;
    int b = bh >> 3, h = bh & 7;
    float2 v = *(const float2*)(k + ((size_t)s * 16 + b) * 512 + h * 64 + 2 * kp);
    g_k[idx] = split2(v.x, v.y);
}

__global__ void __launch_bounds__(256) owprep_kernel(const float* __restrict__ ow) {
    int idx = blockIdx.x * 256 + threadIdx.x;            // over 512*256
    int n = idx >> 8, kp = idx & 255;
    float2 v = *(const float2*)(ow + (size_t)n * 512 + 2 * kp);
    g_ow[idx] = split2(v.x, v.y);
}

// ---------------- vproj (fp32, round-2 style) -----------------
__device__ __forceinline__ void load_T64(float* sm, const float* __restrict__ g, int gpitch) {
#pragma unroll
    for (int i = threadIdx.x; i < 1024; i += 256) {
        int r = i >> 4, j = (i & 15) << 2;
        float4 v = *(const float4*)(g + (size_t)r * gpitch + j);
        sm[(j + 0) * 68 + r] = v.x;
        sm[(j + 1) * 68 + r] = v.y;
        sm[(j + 2) * 68 + r] = v.z;
        sm[(j + 3) * 68 + r] = v.w;
    }
}

__global__ void __launch_bounds__(256) vproj_kernel(const float* __restrict__ keys,
                                                    const float* __restrict__ vw,
                                                    const float* __restrict__ vb) {
    __shared__ float a_sm[64 * 68];
    __shared__ float w_sm[64 * 68];
    const size_t rowbase = (size_t)blockIdx.x * 64;
    load_T64(a_sm, keys + rowbase * 64, 64);
    load_T64(w_sm, vw, 64);
    __syncthreads();

    const int ty = threadIdx.x >> 4, tx = threadIdx.x & 15;
    const int r0 = ty * 4, c0 = tx * 4;
    float4 bias = *(const float4*)(vb + c0);
    float acc[4][4];
#pragma unroll
    for (int rr = 0; rr < 4; rr++) {
        acc[rr][0] = bias.x; acc[rr][1] = bias.y; acc[rr][2] = bias.z; acc[rr][3] = bias.w;
    }
#pragma unroll 8
    for (int j = 0; j < 64; j++) {
        float4 a = *(const float4*)&a_sm[j * 68 + r0];
        float4 w = *(const float4*)&w_sm[j * 68 + c0];
        float av[4] = {a.x, a.y, a.z, a.w}, wv[4] = {w.x, w.y, w.z, w.w};
#pragma unroll
        for (int rr = 0; rr < 4; rr++)
#pragma unroll
            for (int cc = 0; cc < 4; cc++) acc[rr][cc] = fmaf(av[rr], wv[cc], acc[rr][cc]);
    }
#pragma unroll
    for (int rr = 0; rr < 4; rr++)
        *(float4*)(g_vh + (rowbase + r0 + rr) * 64 + c0) =
            make_float4(acc[rr][0], acc[rr][1], acc[rr][2], acc[rr][3]);
}

// ---------------- vtprep: g_vh -> g_vt (transpose + split) -----------------
__global__ void __launch_bounds__(256) vtprep_kernel() {
    __shared__ float st[128 * 68];
    const int bh = blockIdx.x, ch = blockIdx.y;  // s chunk of 128
    const int b = bh >> 3, h = bh & 7;
    const int s0 = ch * 128;
    for (int i = threadIdx.x; i < 128 * 16; i += 256) {
        int r = i >> 4, j = (i & 15) << 2;
        *(float4*)&st[r * 68 + j] =
            *(const float4*)&g_vh[((size_t)(s0 + r) * 16 + b) * 512 + h * 64 + j];
    }
    __syncthreads();
    for (int i = threadIdx.x; i < 64 * 64; i += 256) {
        int d = i >> 6, sp = i & 63;
        g_vt[((size_t)bh * 64 + d) * 512 + ch * 64 + sp] =
            split2(st[(2 * sp) * 68 + d], st[(2 * sp + 1) * 68 + d]);
    }
}

// ---------------- flash attention (tensor core bf16x3) -----------------
__global__ void __launch_bounds__(256) attn_kernel(const unsigned* __restrict__ mask) {
    extern __shared__ uint2 sm2[];
    uint2* k_sm = sm2;               // [128][36] (also Q staging)
    uint2* v_sm = sm2 + 128 * 36;    // [64][68]

    const int tid = threadIdx.x, wid = tid >> 5, lane = tid & 31;
    const int g = lane >> 2, lam = lane & 3;
    const int t0 = blockIdx.x * 128, h = blockIdx.y, b = blockIdx.z;
    const int bh = b * 8 + h;
    const int wt = wid * 16;

    // stage Q tile, extract A-fragments
    for (int i = tid; i < 128 * 32; i += 256) {
        int r = i >> 5, kp = i & 31;
        k_sm[r * 36 + kp] = g_q[((size_t)bh * 512 + t0 + r) * 32 + kp];
    }
    __syncthreads();
    unsigned qh[4][4], ql[4][4];
#pragma unroll
    for (int kt = 0; kt < 4; kt++) {
        int row = wt + g;
        uint2 A0 = k_sm[row * 36 + 8 * kt + lam];
        uint2 A1 = k_sm[(row + 8) * 36 + 8 * kt + lam];
        uint2 A2 = k_sm[row * 36 + 8 * kt + 4 + lam];
        uint2 A3 = k_sm[(row + 8) * 36 + 8 * kt + 4 + lam];
        qh[kt][0] = A0.x; qh[kt][1] = A1.x; qh[kt][2] = A2.x; qh[kt][3] = A3.x;
        ql[kt][0] = A0.y; ql[kt][1] = A1.y; ql[kt][2] = A2.y; ql[kt][3] = A3.y;
    }

    float oacc[8][4];
#pragma unroll
    for (int nt = 0; nt < 8; nt++)
#pragma unroll
        for (int c = 0; c < 4; c++) oacc[nt][c] = 0.0f;
    float mA = -1e30f, mB = -1e30f, lA = 0.0f, lB = 0.0f;

    const unsigned* mrowA = mask + ((size_t)b * Tn + t0 + wt + g) * Sn + 2 * lam;
    const unsigned* mrowB = mrowA + 8 * Sn;

    for (int st = 0; st < 8; st++) {
        const int s0 = st * 128;
        __syncthreads();
        for (int i = tid; i < 128 * 32; i += 256) {
            int r = i >> 5, kp = i & 31;
            k_sm[r * 36 + kp] = g_k[((size_t)bh * 1024 + s0 + r) * 32 + kp];
        }
        for (int i = tid; i < 64 * 64; i += 256) {
            int r = i >> 6, sp = i & 63;
            v_sm[r * 68 + sp] = g_vt[((size_t)bh * 64 + r) * 512 + st * 64 + sp];
        }
        __syncthreads();

        // scores: 16 n-tiles (8 cols each), 4 k-tiles, bf16x3
        float sc[16][4];
#pragma unroll
        for (int j = 0; j < 16; j++) {
            sc[j][0] = sc[j][1] = sc[j][2] = sc[j][3] = 0.0f;
#pragma unroll
            for (int kt = 0; kt < 4; kt++) {
                uint2 B0 = k_sm[(8 * j + g) * 36 + 8 * kt + lam];
                uint2 B1 = k_sm[(8 * j + g) * 36 + 8 * kt + 4 + lam];
                mma(sc[j], qh[kt], B0.x, B1.x);
                mma(sc[j], ql[kt], B0.x, B1.x);
                mma(sc[j], qh[kt], B0.y, B1.y);
            }
        }

        // mask (nonzero u32 = keep)
#pragma unroll
        for (int j = 0; j < 16; j++) {
            uint2 ma = *(const uint2*)(mrowA + s0 + 8 * j);
            uint2 mb = *(const uint2*)(mrowB + s0 + 8 * j);
            if (!ma.x) sc[j][0] = -1e30f;
            if (!ma.y) sc[j][1] = -1e30f;
            if (!mb.x) sc[j][2] = -1e30f;
            if (!mb.y) sc[j][3] = -1e30f;
        }

        // online softmax: rows (wt+g) and (wt+g+8); quad lanes share a row
        float mxA = -1e30f, mxB = -1e30f;
#pragma unroll
        for (int j = 0; j < 16; j++) {
            mxA = fmaxf(mxA, fmaxf(sc[j][0], sc[j][1]));
            mxB = fmaxf(mxB, fmaxf(sc[j][2], sc[j][3]));
        }
        mxA = fmaxf(mxA, __shfl_xor_sync(0xffffffffu, mxA, 1));
        mxA = fmaxf(mxA, __shfl_xor_sync(0xffffffffu, mxA, 2));
        mxB = fmaxf(mxB, __shfl_xor_sync(0xffffffffu, mxB, 1));
        mxB = fmaxf(mxB, __shfl_xor_sync(0xffffffffu, mxB, 2));
        float mnA = fmaxf(mA, mxA), mnB = fmaxf(mB, mxB);
        float aA = __expf(mA - mnA), aB = __expf(mB - mnB);
        mA = mnA; mB = mnB;
#pragma unroll
        for (int nt = 0; nt < 8; nt++) {
            oacc[nt][0] *= aA; oacc[nt][1] *= aA;
            oacc[nt][2] *= aB; oacc[nt][3] *= aB;
        }

        // exp + pack P into A-fragments (hi/lo planes)
        unsigned phi[8][4], plo[8][4];
        float sA = 0.0f, sB = 0.0f;
#pragma unroll
        for (int j = 0; j < 16; j++) {
            int kt = j >> 1, sl = (j & 1) * 2;
            float p0 = __expf(sc[j][0] - mA);
            float p1 = __expf(sc[j][1] - mA);
            float p2 = __expf(sc[j][2] - mB);
            float p3 = __expf(sc[j][3] - mB);
            sA += p0 + p1; sB += p2 + p3;
            unsigned hw0 = pk(p0, p1);
            phi[kt][sl] = hw0;
            plo[kt][sl] = pk(p0 - bflo(hw0), p1 - bfhi(hw0));
            unsigned hw1 = pk(p2, p3);
            phi[kt][sl + 1] = hw1;
            plo[kt][sl + 1] = pk(p2 - bflo(hw1), p3 - bfhi(hw1));
        }
        sA += __shfl_xor_sync(0xffffffffu, sA, 1);
        sA += __shfl_xor_sync(0xffffffffu, sA, 2);
        sB += __shfl_xor_sync(0xffffffffu, sB, 1);
        sB += __shfl_xor_sync(0xffffffffu, sB, 2);
        lA = lA * aA + sA;
        lB = lB * aB + sB;

        // O += P @ V^T-tiles
#pragma unroll
        for (int nt = 0; nt < 8; nt++) {
#pragma unroll
            for (int kt = 0; kt < 8; kt++) {
                uint2 B0 = v_sm[(8 * nt + g) * 68 + 8 * kt + lam];
                uint2 B1 = v_sm[(8 * nt + g) * 68 + 8 * kt + 4 + lam];
                mma(oacc[nt], phi[kt], B0.x, B1.x);
                mma(oacc[nt], plo[kt], B0.x, B1.x);
                mma(oacc[nt], phi[kt], B0.y, B1.y);
            }
        }
    }

    // epilogue: normalize, split, store pairs
    float iA = 1.0f / lA, iB = 1.0f / lB;
    int tA = t0 + wt + g;
    int apair = h * 32 + lam;  // + nt*4
#pragma unroll
    for (int nt = 0; nt < 8; nt++) {
        g_va[((size_t)tA * 16 + b) * 256 + apair + nt * 4] =
            split2(oacc[nt][0] * iA, oacc[nt][1] * iA);
        g_va[((size_t)(tA + 8) * 16 + b) * 256 + apair + nt * 4] =
            split2(oacc[nt][2] * iB, oacc[nt][3] * iB);
    }
}

// ---------------- oproj (tensor core bf16x3) -----------------
__global__ void __launch_bounds__(256) oproj_kernel(const float* __restrict__ ob,
                                                    float* __restrict__ out) {
    extern __shared__ uint2 smo[];
    uint2* a_sm = smo;              // [128][36]
    uint2* b_sm = smo + 128 * 36;   // [128][36]

    const int tid = threadIdx.x, wid = tid >> 5, lane = tid & 31;
    const int g = lane >> 2, lam = lane & 3;
    const int mw = wid >> 1, nw = wid & 1;
    const int row0 = blockIdx.x * 128, n0 = blockIdx.y * 128;

    float acc[2][8][4];
#pragma unroll
    for (int mt = 0; mt < 2; mt++)
#pragma unroll
        for (int nt = 0; nt < 8; nt++) {
            float2 bv = *(const float2*)(ob + n0 + nw * 64 + 8 * nt + 2 * lam);
            acc[mt][nt][0] = bv.x; acc[mt][nt][1] = bv.y;
            acc[mt][nt][2] = bv.x; acc[mt][nt][3] = bv.y;
        }

    for (int kc = 0; kc < 8; kc++) {
        __syncthreads();
        for (int i = tid; i < 128 * 32; i += 256) {
            int r = i >> 5, kp = i & 31;
            a_sm[r * 36 + kp] = g_va[(size_t)(row0 + r) * 256 + 32 * kc + kp];
            b_sm[r * 36 + kp] = g_ow[(size_t)(n0 + r) * 256 + 32 * kc + kp];
        }
        __syncthreads();

        unsigned ah[2][4][4], al[2][4][4];
#pragma unroll
        for (int mt = 0; mt < 2; mt++)
#pragma unroll
            for (int kt = 0; kt < 4; kt++) {
                int row = mw * 32 + mt * 16 + g;
                uint2 A0 = a_sm[row * 36 + 8 * kt + lam];
                uint2 A1 = a_sm[(row + 8) * 36 + 8 * kt + lam];
                uint2 A2 = a_sm[row * 36 + 8 * kt + 4 + lam];
                uint2 A3 = a_sm[(row + 8) * 36 + 8 * kt + 4 + lam];
                ah[mt][kt][0] = A0.x; ah[mt][kt][1] = A1.x; ah[mt][kt][2] = A2.x; ah[mt][kt][3] = A3.x;
                al[mt][kt][0] = A0.y; al[mt][kt][1] = A1.y; al[mt][kt][2] = A2.y; al[mt][kt][3] = A3.y;
            }

#pragma unroll
        for (int nt = 0; nt < 8; nt++)
#pragma unroll
            for (int kt = 0; kt < 4; kt++) {
                uint2 B0 = b_sm[(nw * 64 + 8 * nt + g) * 36 + 8 * kt + lam];
                uint2 B1 = b_sm[(nw * 64 + 8 * nt + g) * 36 + 8 * kt + 4 + lam];
#pragma unroll
                for (int mt = 0; mt < 2; mt++) {
                    mma(acc[mt][nt], ah[mt][kt], B0.x, B1.x);
                    mma(acc[mt][nt], al[mt][kt], B0.x, B1.x);
                    mma(acc[mt][nt], ah[mt][kt], B0.y, B1.y);
                }
            }
    }

#pragma unroll
    for (int mt = 0; mt < 2; mt++)
#pragma unroll
        for (int nt = 0; nt < 8; nt++) {
            int row = row0 + mw * 32 + mt * 16 + g;
            int col = n0 + nw * 64 + 8 * nt + 2 * lam;
            *(float2*)&out[(size_t)row * 512 + col] = make_float2(acc[mt][nt][0], acc[mt][nt][1]);
            *(float2*)&out[(size_t)(row + 8) * 512 + col] = make_float2(acc[mt][nt][2], acc[mt][nt][3]);
        }
}

// ---------------------------------------------------------------------------
extern "C" void kernel_launch(void* const* d_in, const int* in_sizes, int n_in,
                              void* d_out, int out_size) {
    const float* q = (const float*)d_in[0];
    const float* k = (const float*)d_in[1];
    const unsigned* mask = (const unsigned*)d_in[2];
    const float* vw = (const float*)d_in[3];
    const float* vb = (const float*)d_in[4];
    const float* ow = (const float*)d_in[5];
    const float* ob = (const float*)d_in[6];
    float* out = (float*)d_out;

    qprep_kernel<<<(128 * 512 * 32) / 256, 256>>>(q);
    kprep_kernel<<<(128 * 1024 * 32) / 256, 256>>>(k);
    owprep_kernel<<<(512 * 256) / 256, 256>>>(ow);
    vproj_kernel<<<(Sn * Bn * Hn) / 64, 256>>>(k, vw, vb);
    vtprep_kernel<<<dim3(128, 8), 256>>>();

    const int attn_smem = (128 * 36 + 64 * 68) * sizeof(uint2);  // 71680
    cudaFuncSetAttribute(attn_kernel, cudaFuncAttributeMaxDynamicSharedMemorySize, attn_smem);
    attn_kernel<<<dim3(4, 8, 16), 256, attn_smem>>>(mask);

    const int oproj_smem = 2 * 128 * 36 * sizeof(uint2);  // 73728
    cudaFuncSetAttribute(oproj_kernel, cudaFuncAttributeMaxDynamicSharedMemorySize, oproj_smem);
    oproj_kernel<<<dim3(64, 4), 256, oproj_smem>>>(ob, out);
}